// round 3
// baseline (speedup 1.0000x reference)
#include <cuda_runtime.h>
#include <math.h>

#define Bn 32
#define Sn 2048
#define En 1024
#define An 512
#define NCHUNK 16   // S split for pass-2 partials

// Scratch (allocation-free rule: __device__ globals)
__device__ float g_D[Bn * An];            // b_enc + b_dec + dec@W_dec   [32,512]
__device__ float g_scores[Bn * Sn];       // raw scores                  [32,2048]
__device__ float g_weights[Bn * Sn];      // softmax weights             [32,2048]
__device__ float g_partial[Bn * NCHUNK * En]; // partial weighted enc sums
__device__ int   g_maskmode;              // 0 = 4-byte elems, 1 = 1-byte elems

// ---------------------------------------------------------------------------
// K-1: detect mask element width. For int32/float32 0/1 encodings, bytes at
// offset %4==1 are always zero; for byte-bool they are ~50% nonzero over 16K
// samples. Deterministic pure function of the input.
// ---------------------------------------------------------------------------
__global__ void k_detect_mask(const unsigned char* __restrict__ m) {
    int t = threadIdx.x;
    int found = 0;
    for (int i = 4 * t + 1; i < Bn * Sn; i += 1024)
        if (m[i]) found = 1;
    found = __syncthreads_or(found);
    if (t == 0) g_maskmode = found;
}

// ---------------------------------------------------------------------------
// K0: g_D[b,a] = b_enc[a] + b_dec[a] + decoder_hidden[b,:] @ W_dec[:,a]
// ---------------------------------------------------------------------------
__global__ void k0_decoder(const float* __restrict__ dec,
                           const float* __restrict__ Wd,
                           const float* __restrict__ bd,
                           const float* __restrict__ be) {
    int b = blockIdx.x, t = threadIdx.x;
    __shared__ float ds[512];
    ds[t]       = dec[b * 512 + t];
    ds[t + 256] = dec[b * 512 + t + 256];
    __syncthreads();
#pragma unroll
    for (int a0 = 0; a0 < 2; a0++) {
        int a = t + a0 * 256;
        float acc = be[a] + bd[a];
#pragma unroll 8
        for (int h = 0; h < 512; h++) acc += ds[h] * Wd[h * 512 + a];
        g_D[b * 512 + a] = acc;
    }
}

// ---------------------------------------------------------------------------
// K1: for 32 rows per CTA, compute ea = enc_row @ W_enc (K=1024, N=512 in regs
// via packed f32x2 FMA), then score = sum_a tanh(ea + g_D) * W_att + b_att.
// Thread microtile: 8 rows x 8 cols (as 4 f32x2 pairs). 256 threads = 4 row
// groups x 64 col groups.
// ---------------------------------------------------------------------------
__global__ __launch_bounds__(256, 2)
void k1_scores(const float* __restrict__ enc,
               const float* __restrict__ We,
               const float* __restrict__ Wa,
               const float* __restrict__ ba) {
    __shared__ float  As[16][33];       // [k][row], padded
    __shared__ float4 Ws4[16 * 128];    // [k][col/4]  (32 KB)
    __shared__ float  s_score[32];

    const int tid = threadIdx.x;
    const int r0  = blockIdx.x * 32;
    const int b   = r0 >> 11;           // row / 2048
    const int rg  = tid >> 6;           // 0..3  -> rows rg*8 .. rg*8+7
    const int cg  = tid & 63;           // 0..63 -> cols 4cg..4cg+3, 256+4cg..+3

    if (tid < 32) s_score[tid] = 0.f;

    unsigned long long acc[8][4];
#pragma unroll
    for (int i = 0; i < 8; i++)
#pragma unroll
        for (int j = 0; j < 4; j++) acc[i][j] = 0ull;

    for (int kc = 0; kc < 64; kc++) {
        __syncthreads();
        // load W chunk: 16 k-rows x 512 cols
        const float4* Wg4 = reinterpret_cast<const float4*>(We + kc * 16 * 512);
#pragma unroll
        for (int v = 0; v < 8; v++) Ws4[v * 256 + tid] = Wg4[v * 256 + tid];
        // load A chunk transposed: 32 rows x 16 k
        if (tid < 128) {
            int row = tid >> 2, kkb = (tid & 3) * 4;
            float4 g = *reinterpret_cast<const float4*>(
                enc + (size_t)(r0 + row) * 1024 + kc * 16 + kkb);
            As[kkb + 0][row] = g.x;
            As[kkb + 1][row] = g.y;
            As[kkb + 2][row] = g.z;
            As[kkb + 3][row] = g.w;
        }
        __syncthreads();

#pragma unroll
        for (int kk = 0; kk < 16; kk++) {
            unsigned long long aa[8];
#pragma unroll
            for (int i = 0; i < 8; i++) {
                float av = As[kk][rg * 8 + i];
                asm("mov.b64 %0, {%1,%1};" : "=l"(aa[i]) : "f"(av));
            }
            const ulonglong2* wp =
                reinterpret_cast<const ulonglong2*>(Ws4 + kk * 128);
            ulonglong2 wA = wp[cg];
            ulonglong2 wB = wp[cg + 64];
            unsigned long long wv0 = wA.x, wv1 = wA.y, wv2 = wB.x, wv3 = wB.y;
#pragma unroll
            for (int i = 0; i < 8; i++) {
                asm("fma.rn.f32x2 %0, %1, %2, %0;" : "+l"(acc[i][0]) : "l"(aa[i]), "l"(wv0));
                asm("fma.rn.f32x2 %0, %1, %2, %0;" : "+l"(acc[i][1]) : "l"(aa[i]), "l"(wv1));
                asm("fma.rn.f32x2 %0, %1, %2, %0;" : "+l"(acc[i][2]) : "l"(aa[i]), "l"(wv2));
                asm("fma.rn.f32x2 %0, %1, %2, %0;" : "+l"(acc[i][3]) : "l"(aa[i]), "l"(wv3));
            }
        }
    }

    // Epilogue: tanh + dot with W_att, reduce over cols
    float dv[8], wv[8];
#pragma unroll
    for (int jj = 0; jj < 8; jj++) {
        int col = (jj < 4) ? (4 * cg + jj) : (256 + 4 * cg + (jj - 4));
        dv[jj] = g_D[b * 512 + col];
        wv[jj] = Wa[col];
    }
    float part[8];
#pragma unroll
    for (int i = 0; i < 8; i++) {
        float p = 0.f;
#pragma unroll
        for (int j = 0; j < 4; j++) {
            float lo, hi;
            asm("mov.b64 {%0,%1}, %2;" : "=f"(lo), "=f"(hi) : "l"(acc[i][j]));
            int jj = j * 2;
            p += tanhf(lo + dv[jj])     * wv[jj];
            p += tanhf(hi + dv[jj + 1]) * wv[jj + 1];
        }
        part[i] = p;
    }
#pragma unroll
    for (int i = 0; i < 8; i++) {
#pragma unroll
        for (int off = 16; off > 0; off >>= 1)
            part[i] += __shfl_xor_sync(0xffffffffu, part[i], off);
    }
    if ((tid & 31) == 0) {
#pragma unroll
        for (int i = 0; i < 8; i++) atomicAdd(&s_score[rg * 8 + i], part[i]);
    }
    __syncthreads();
    if (tid < 32) g_scores[r0 + tid] = s_score[tid] + ba[0];
}

// ---------------------------------------------------------------------------
// K2a: masked softmax over S per batch. Mask test works for int32 (0/1),
// float32 (0.0/1.0) via 32-bit word != 0, or byte-bool via g_maskmode.
// ---------------------------------------------------------------------------
__global__ void k2a_softmax(const void* __restrict__ masks) {
    int b = blockIdx.x, t = threadIdx.x;
    __shared__ float sm[2048];
    __shared__ float red[256];
    const float NEG_INF = __int_as_float(0xff800000);
    const int mode = g_maskmode;
    const unsigned int*  m32 = (const unsigned int*)masks;
    const unsigned char* m8  = (const unsigned char*)masks;

    float lmax = NEG_INF;
#pragma unroll
    for (int v = 0; v < 8; v++) {
        int idx = v * 256 + t;
        float sc = g_scores[b * 2048 + idx];
        bool masked = mode ? (m8[b * 2048 + idx] != 0)
                           : (m32[b * 2048 + idx] != 0u);
        if (masked) sc = NEG_INF;
        sm[idx] = sc;
        lmax = fmaxf(lmax, sc);
    }
    red[t] = lmax;
    __syncthreads();
    for (int o = 128; o > 0; o >>= 1) {
        if (t < o) red[t] = fmaxf(red[t], red[t + o]);
        __syncthreads();
    }
    float bmax = red[0];
    __syncthreads();

    float lsum = 0.f;
#pragma unroll
    for (int v = 0; v < 8; v++) {
        int idx = v * 256 + t;
        float e = expf(sm[idx] - bmax);
        sm[idx] = e;
        lsum += e;
    }
    red[t] = lsum;
    __syncthreads();
    for (int o = 128; o > 0; o >>= 1) {
        if (t < o) red[t] += red[t + o];
        __syncthreads();
    }
    float inv = 1.f / red[0];
#pragma unroll
    for (int v = 0; v < 8; v++) {
        int idx = v * 256 + t;
        g_weights[b * 2048 + idx] = sm[idx] * inv;
    }
}

// ---------------------------------------------------------------------------
// K2b: partial[b,chunk,:] = sum_{s in chunk} w[b,s] * enc[b,s,:]
// grid (NCHUNK, B); skips zero-weight (masked) rows.
// ---------------------------------------------------------------------------
__global__ void k2b_partial(const float* __restrict__ enc) {
    int ch = blockIdx.x, b = blockIdx.y, t = threadIdx.x;
    __shared__ float w[128];
    if (t < 128) w[t] = g_weights[b * 2048 + ch * 128 + t];
    __syncthreads();

    const float4* rowbase =
        reinterpret_cast<const float4*>(enc) + (size_t)(b * 2048 + ch * 128) * 256;
    float4 acc = make_float4(0.f, 0.f, 0.f, 0.f);
    for (int si = 0; si < 128; si++) {
        float wv = w[si];
        if (wv != 0.f) {
            float4 v = rowbase[si * 256 + t];
            acc.x += wv * v.x;
            acc.y += wv * v.y;
            acc.z += wv * v.z;
            acc.w += wv * v.w;
        }
    }
    reinterpret_cast<float4*>(g_partial)[(b * NCHUNK + ch) * 256 + t] = acc;
}

// ---------------------------------------------------------------------------
// K2c: ctx1024 = sum of partials; out[b,:] = ctx1024 @ W_enc + b_enc
// ---------------------------------------------------------------------------
__global__ void k2c_context(const float* __restrict__ We,
                            const float* __restrict__ be,
                            float* __restrict__ out) {
    int b = blockIdx.x, t = threadIdx.x;
    __shared__ float ctx[1024];
    float4 s = make_float4(0.f, 0.f, 0.f, 0.f);
#pragma unroll
    for (int chn = 0; chn < NCHUNK; chn++) {
        float4 v = reinterpret_cast<const float4*>(g_partial)[(b * NCHUNK + chn) * 256 + t];
        s.x += v.x; s.y += v.y; s.z += v.z; s.w += v.w;
    }
    reinterpret_cast<float4*>(ctx)[t] = s;
    __syncthreads();

    float acc0 = be[t], acc1 = be[t + 256];
#pragma unroll 4
    for (int k = 0; k < 1024; k++) {
        float c = ctx[k];
        const float* wr = We + k * 512;
        acc0 += c * wr[t];
        acc1 += c * wr[t + 256];
    }
    out[b * 512 + t]       = acc0;
    out[b * 512 + t + 256] = acc1;
}

// ---------------------------------------------------------------------------
extern "C" void kernel_launch(void* const* d_in, const int* in_sizes, int n_in,
                              void* d_out, int out_size) {
    const float*         enc   = (const float*)d_in[0];
    const float*         dec   = (const float*)d_in[1];
    const unsigned char* masks = (const unsigned char*)d_in[2];
    const float*         We    = (const float*)d_in[3];
    const float*         be    = (const float*)d_in[4];
    const float*         Wd    = (const float*)d_in[5];
    const float*         bd    = (const float*)d_in[6];
    const float*         Wa    = (const float*)d_in[7];
    const float*         ba    = (const float*)d_in[8];
    float* out = (float*)d_out;

    k_detect_mask<<<1, 256>>>(masks);
    k0_decoder<<<Bn, 256>>>(dec, Wd, bd, be);
    k1_scores<<<(Bn * Sn) / 32, 256>>>(enc, We, Wa, ba);
    k2a_softmax<<<Bn, 256>>>((const void*)masks);
    dim3 g2b(NCHUNK, Bn);
    k2b_partial<<<g2b, 256>>>(enc);
    k2c_context<<<Bn, 256>>>(We, be, out);
}

// round 5
// speedup vs baseline: 1.6576x; 1.6576x over previous
#include <cuda_runtime.h>
#include <cuda_bf16.h>
#include <math.h>
#include <stdint.h>

#define Bn 32
#define Sn 2048
#define NCHUNK 16

// ------------------------------ device scratch ------------------------------
__device__ float g_D[Bn * 512];
__device__ float g_scores[Bn * Sn];
__device__ float g_weights[Bn * Sn];
__device__ float g_partial[Bn * NCHUNK * 1024];
__device__ int   g_maskmode;
// W_enc staged as bf16 hi/lo, SW128-swizzled [n][k] tiles.
// 32 pieces (nc 0..1 x kc 0..15), each 64KB = [hi 32KB][lo 32KB]
__device__ __align__(16) unsigned char g_Bt[32 * 65536];

// ------------------------------ helpers -------------------------------------
__device__ __forceinline__ uint32_t smem_u32(const void* p) {
    uint32_t a;
    asm("{ .reg .u64 t; cvta.to.shared.u64 t, %1; cvt.u32.u64 %0, t; }"
        : "=r"(a) : "l"(p));
    return a;
}
__device__ __forceinline__ uint32_t swz(uint32_t off) {
    return off ^ ((off >> 3) & 0x70);
}
__device__ __forceinline__ uint32_t lds32(uint32_t a) {
    uint32_t v;
    asm("ld.shared.b32 %0, [%1];" : "=r"(v) : "r"(a));
    return v;
}
__device__ __forceinline__ void mma_bf16(float* c, const uint32_t* a,
                                         uint32_t b0, uint32_t b1) {
    asm("mma.sync.aligned.m16n8k16.row.col.f32.bf16.bf16.f32 "
        "{%0,%1,%2,%3},{%4,%5,%6,%7},{%8,%9},{%0,%1,%2,%3};"
        : "+f"(c[0]), "+f"(c[1]), "+f"(c[2]), "+f"(c[3])
        : "r"(a[0]), "r"(a[1]), "r"(a[2]), "r"(a[3]), "r"(b0), "r"(b1));
}
__device__ __forceinline__ void cp16(uint32_t dst, const void* src) {
    asm volatile("cp.async.cg.shared.global [%0], [%1], 16;"
                 :: "r"(dst), "l"(src));
}
__device__ __forceinline__ void cp_commit() {
    asm volatile("cp.async.commit_group;" ::: "memory");
}
__device__ __forceinline__ void cp_wait0() {
    asm volatile("cp.async.wait_group 0;" ::: "memory");
}

// ------------------------------ mask detect ---------------------------------
__global__ void k_detect_mask(const unsigned char* __restrict__ m) {
    int t = threadIdx.x;
    int found = 0;
    for (int i = 4 * t + 1; i < Bn * Sn; i += 1024)
        if (m[i]) found = 1;
    found = __syncthreads_or(found);
    if (t == 0) g_maskmode = found;
}

// ------------------------------ k0: decoder att -----------------------------
__global__ void k0_decoder(const float* __restrict__ dec,
                           const float* __restrict__ Wd,
                           const float* __restrict__ bd,
                           const float* __restrict__ be) {
    int b = blockIdx.x, t = threadIdx.x;
    __shared__ float ds[512];
    ds[t]       = dec[b * 512 + t];
    ds[t + 256] = dec[b * 512 + t + 256];
    __syncthreads();
#pragma unroll
    for (int a0 = 0; a0 < 2; a0++) {
        int a = t + a0 * 256;
        float acc = be[a] + bd[a];
#pragma unroll 8
        for (int h = 0; h < 512; h++) acc += ds[h] * Wd[h * 512 + a];
        g_D[b * 512 + a] = acc;
    }
}

// ------------------------------ kW: stage W_enc -----------------------------
// piece = nc*16 + kc: tile[nl][kl], SW128 swizzled, hi at +0, lo at +32KB
__global__ void kW_convert(const float* __restrict__ We) {
    int gid = blockIdx.x * 256 + threadIdx.x;   // 0..524287
    int k = gid >> 9, n = gid & 511;
    float w = We[gid];
    __nv_bfloat16 hi = __float2bfloat16(w);
    float rem = w - __bfloat162float(hi);
    __nv_bfloat16 lo = __float2bfloat16(rem);
    int kc = k >> 6, kl = k & 63, nc = n >> 8, nl = n & 255;
    int piece = nc * 16 + kc;
    uint32_t sw = swz((uint32_t)nl * 128u + (uint32_t)kl * 2u);
    unsigned char* basep = g_Bt + (size_t)piece * 65536;
    *(__nv_bfloat16*)(basep + sw)         = hi;
    *(__nv_bfloat16*)(basep + 32768 + sw) = lo;
}

// ------------------------------ K1: HMMA scores -----------------------------
// Dynamic smem: 2 buffers x (A 32KB + B 64KB) = 192KB
#define SA_OFF 0
#define SB_OFF 32768
#define BUFSTRIDE 98304
#define SM_SMEM (2 * BUFSTRIDE)

__device__ __forceinline__ void convertA64(const float* __restrict__ enc,
                                           int r0, int kc, char* abuf, int tid) {
    const float4* src = (const float4*)(enc + (size_t)r0 * 1024 + kc * 64);
#pragma unroll
    for (int i = 0; i < 8; i++) {
        int idx = i * 256 + tid;           // 0..2047
        int row = idx >> 4, kq = idx & 15; // kq = float4 index within 64 floats
        float4 f = src[(size_t)row * 256 + kq];
        __nv_bfloat16 h0 = __float2bfloat16(f.x), h1 = __float2bfloat16(f.y);
        __nv_bfloat16 h2 = __float2bfloat16(f.z), h3 = __float2bfloat16(f.w);
        __nv_bfloat16 l0 = __float2bfloat16(f.x - __bfloat162float(h0));
        __nv_bfloat16 l1 = __float2bfloat16(f.y - __bfloat162float(h1));
        __nv_bfloat16 l2 = __float2bfloat16(f.z - __bfloat162float(h2));
        __nv_bfloat16 l3 = __float2bfloat16(f.w - __bfloat162float(h3));
        __nv_bfloat162 ph0 = __nv_bfloat162(h0, h1), ph1 = __nv_bfloat162(h2, h3);
        __nv_bfloat162 pl0 = __nv_bfloat162(l0, l1), pl1 = __nv_bfloat162(l2, l3);
        uint32_t sw = swz((uint32_t)row * 128u + (uint32_t)kq * 8u);
        *(uint2*)(abuf + sw)         = make_uint2(*(uint32_t*)&ph0, *(uint32_t*)&ph1);
        *(uint2*)(abuf + 16384 + sw) = make_uint2(*(uint32_t*)&pl0, *(uint32_t*)&pl1);
    }
}

__global__ __launch_bounds__(256)
void k1_mma(const float* __restrict__ enc,
            const float* __restrict__ Wa,
            const float* __restrict__ ba) {
    extern __shared__ char smem[];
    __shared__ float s_sc[128];
    const uint32_t sb = smem_u32(smem);
    const int tid = threadIdx.x;
    const int wid = tid >> 5, lid = tid & 31;
    const int r0 = blockIdx.x * 128;
    const int b  = r0 >> 11;
    const int wm = wid & 3, wn = wid >> 2;
    const int r4 = lid >> 2, q = lid & 3;

    if (tid < 128) s_sc[tid] = 0.f;

    for (int nc = 0; nc < 2; nc++) {
        float acc[2][16][4];
#pragma unroll
        for (int mt = 0; mt < 2; mt++)
#pragma unroll
            for (int nt = 0; nt < 16; nt++)
#pragma unroll
                for (int v = 0; v < 4; v++) acc[mt][nt][v] = 0.f;

        // prologue: stage kc=0
        {
            const unsigned char* src = g_Bt + (size_t)(nc * 16) * 65536;
#pragma unroll
            for (int v = 0; v < 16; v++)
                cp16(sb + SB_OFF + (v * 256 + tid) * 16, src + (size_t)(v * 256 + tid) * 16);
            cp_commit();
            convertA64(enc, r0, 0, smem + SA_OFF, tid);
            cp_wait0();
        }
        __syncthreads();

        for (int kc = 0; kc < 16; kc++) {
            const int cur = kc & 1;
            const uint32_t aB = sb + cur * BUFSTRIDE + SA_OFF;
            const uint32_t bB = sb + cur * BUFSTRIDE + SB_OFF;

            if (kc < 15) {  // async-stage next B while MMA runs
                const unsigned char* src = g_Bt + (size_t)(nc * 16 + kc + 1) * 65536;
                uint32_t dst = sb + (cur ^ 1) * BUFSTRIDE + SB_OFF;
#pragma unroll
                for (int v = 0; v < 16; v++)
                    cp16(dst + (v * 256 + tid) * 16, src + (size_t)(v * 256 + tid) * 16);
                cp_commit();
            }

#pragma unroll
            for (int kk = 0; kk < 4; kk++) {
                uint32_t ah[2][4], al[2][4];
#pragma unroll
                for (int mt = 0; mt < 2; mt++) {
                    uint32_t o0 = (uint32_t)(wm * 32 + mt * 16 + r4) * 128u +
                                  (uint32_t)(kk * 32 + q * 4);
                    ah[mt][0] = lds32(aB + swz(o0));
                    ah[mt][1] = lds32(aB + swz(o0 + 1024));
                    ah[mt][2] = lds32(aB + swz(o0 + 16));
                    ah[mt][3] = lds32(aB + swz(o0 + 1040));
                    al[mt][0] = lds32(aB + 16384 + swz(o0));
                    al[mt][1] = lds32(aB + 16384 + swz(o0 + 1024));
                    al[mt][2] = lds32(aB + 16384 + swz(o0 + 16));
                    al[mt][3] = lds32(aB + 16384 + swz(o0 + 1040));
                }
#pragma unroll
                for (int nt = 0; nt < 16; nt++) {
                    uint32_t ob = (uint32_t)(wn * 128 + nt * 8 + r4) * 128u +
                                  (uint32_t)(kk * 32 + q * 4);
                    uint32_t bh0 = lds32(bB + swz(ob));
                    uint32_t bh1 = lds32(bB + swz(ob + 16));
                    uint32_t bl0 = lds32(bB + 32768 + swz(ob));
                    uint32_t bl1 = lds32(bB + 32768 + swz(ob + 16));
#pragma unroll
                    for (int mt = 0; mt < 2; mt++) {
                        mma_bf16(acc[mt][nt], ah[mt], bh0, bh1);
                        mma_bf16(acc[mt][nt], al[mt], bh0, bh1);
                        mma_bf16(acc[mt][nt], ah[mt], bl0, bl1);
                    }
                }
            }

            if (kc < 15)
                convertA64(enc, r0, kc + 1, smem + (cur ^ 1) * BUFSTRIDE + SA_OFF, tid);
            cp_wait0();
            __syncthreads();
        }

        // epilogue: score += tanh(acc + D[col]) * Wa[col]
#pragma unroll
        for (int mt = 0; mt < 2; mt++) {
            float p0 = 0.f, p1 = 0.f;
#pragma unroll
            for (int nt = 0; nt < 16; nt++) {
                int c0 = nc * 256 + wn * 128 + nt * 8 + q * 2;
                float d0v = g_D[b * 512 + c0], d1v = g_D[b * 512 + c0 + 1];
                float w0 = Wa[c0], w1 = Wa[c0 + 1];
                p0 += tanhf(acc[mt][nt][0] + d0v) * w0 + tanhf(acc[mt][nt][1] + d1v) * w1;
                p1 += tanhf(acc[mt][nt][2] + d0v) * w0 + tanhf(acc[mt][nt][3] + d1v) * w1;
            }
            p0 += __shfl_xor_sync(0xffffffffu, p0, 1);
            p0 += __shfl_xor_sync(0xffffffffu, p0, 2);
            p1 += __shfl_xor_sync(0xffffffffu, p1, 1);
            p1 += __shfl_xor_sync(0xffffffffu, p1, 2);
            if (q == 0) {
                atomicAdd(&s_sc[wm * 32 + mt * 16 + r4], p0);
                atomicAdd(&s_sc[wm * 32 + mt * 16 + r4 + 8], p1);
            }
        }
        __syncthreads();
    }

    if (tid < 128) g_scores[r0 + tid] = s_sc[tid] + ba[0];
}

// ------------------------------ k2a: softmax --------------------------------
__global__ void k2a_softmax(const void* __restrict__ masks) {
    int b = blockIdx.x, t = threadIdx.x;
    __shared__ float sm[2048];
    __shared__ float red[256];
    const float NEG_INF = __int_as_float(0xff800000);
    const int mode = g_maskmode;
    const unsigned int*  m32 = (const unsigned int*)masks;
    const unsigned char* m8  = (const unsigned char*)masks;

    float lmax = NEG_INF;
#pragma unroll
    for (int v = 0; v < 8; v++) {
        int idx = v * 256 + t;
        float sc = g_scores[b * 2048 + idx];
        bool masked = mode ? (m8[b * 2048 + idx] != 0) : (m32[b * 2048 + idx] != 0u);
        if (masked) sc = NEG_INF;
        sm[idx] = sc;
        lmax = fmaxf(lmax, sc);
    }
    red[t] = lmax;
    __syncthreads();
    for (int o = 128; o > 0; o >>= 1) {
        if (t < o) red[t] = fmaxf(red[t], red[t + o]);
        __syncthreads();
    }
    float bmax = red[0];
    __syncthreads();

    float lsum = 0.f;
#pragma unroll
    for (int v = 0; v < 8; v++) {
        int idx = v * 256 + t;
        float e = expf(sm[idx] - bmax);
        sm[idx] = e;
        lsum += e;
    }
    red[t] = lsum;
    __syncthreads();
    for (int o = 128; o > 0; o >>= 1) {
        if (t < o) red[t] += red[t + o];
        __syncthreads();
    }
    float inv = 1.f / red[0];
#pragma unroll
    for (int v = 0; v < 8; v++) {
        int idx = v * 256 + t;
        g_weights[b * 2048 + idx] = sm[idx] * inv;
    }
}

// ------------------------------ k2b: weighted sum ---------------------------
__global__ void k2b_partial(const float* __restrict__ enc) {
    int ch = blockIdx.x, b = blockIdx.y, t = threadIdx.x;
    __shared__ float w[128];
    if (t < 128) w[t] = g_weights[b * 2048 + ch * 128 + t];
    __syncthreads();

    const float4* rowbase =
        reinterpret_cast<const float4*>(enc) + (size_t)(b * 2048 + ch * 128) * 256;
    float4 acc = make_float4(0.f, 0.f, 0.f, 0.f);
    for (int si = 0; si < 128; si++) {
        float wv = w[si];
        if (wv != 0.f) {
            float4 v = rowbase[(size_t)si * 256 + t];
            acc.x += wv * v.x; acc.y += wv * v.y;
            acc.z += wv * v.z; acc.w += wv * v.w;
        }
    }
    reinterpret_cast<float4*>(g_partial)[(b * NCHUNK + ch) * 256 + t] = acc;
}

// ------------------------------ k2c: final GEMV -----------------------------
__global__ void k2c_context(const float* __restrict__ We,
                            const float* __restrict__ be,
                            float* __restrict__ out) {
    int b = blockIdx.x, t = threadIdx.x;
    __shared__ float ctx[1024];
    float4 s = make_float4(0.f, 0.f, 0.f, 0.f);
#pragma unroll
    for (int chn = 0; chn < NCHUNK; chn++) {
        float4 v = reinterpret_cast<const float4*>(g_partial)[(b * NCHUNK + chn) * 256 + t];
        s.x += v.x; s.y += v.y; s.z += v.z; s.w += v.w;
    }
    reinterpret_cast<float4*>(ctx)[t] = s;
    __syncthreads();

    float acc0 = be[t], acc1 = be[t + 256];
#pragma unroll 4
    for (int k = 0; k < 1024; k++) {
        float c = ctx[k];
        const float* wr = We + k * 512;
        acc0 += c * wr[t];
        acc1 += c * wr[t + 256];
    }
    out[b * 512 + t]       = acc0;
    out[b * 512 + t + 256] = acc1;
}

// ---------------------------------------------------------------------------
extern "C" void kernel_launch(void* const* d_in, const int* in_sizes, int n_in,
                              void* d_out, int out_size) {
    const float*         enc   = (const float*)d_in[0];
    const float*         dec   = (const float*)d_in[1];
    const unsigned char* masks = (const unsigned char*)d_in[2];
    const float*         We    = (const float*)d_in[3];
    const float*         be    = (const float*)d_in[4];
    const float*         Wd    = (const float*)d_in[5];
    const float*         bd    = (const float*)d_in[6];
    const float*         Wa    = (const float*)d_in[7];
    const float*         ba    = (const float*)d_in[8];
    float* out = (float*)d_out;

    static int configured = 0;
    if (!configured) {
        cudaFuncSetAttribute(k1_mma, cudaFuncAttributeMaxDynamicSharedMemorySize, SM_SMEM);
        configured = 1;
    }

    k_detect_mask<<<1, 256>>>(masks);
    k0_decoder<<<Bn, 256>>>(dec, Wd, bd, be);
    kW_convert<<<2048, 256>>>(We);
    k1_mma<<<512, 256, SM_SMEM>>>(enc, Wa, ba);
    k2a_softmax<<<Bn, 256>>>((const void*)masks);
    dim3 g2b(NCHUNK, Bn);
    k2b_partial<<<g2b, 256>>>(enc);
    k2c_context<<<Bn, 256>>>(We, be, out);
}

// round 6
// speedup vs baseline: 1.9031x; 1.1481x over previous
#include <cuda_runtime.h>
#include <cuda_bf16.h>
#include <math.h>
#include <stdint.h>

#define Bn 32
#define Sn 2048
#define NCHUNK 16

// ------------------------------ device scratch ------------------------------
__device__ float g_D[Bn * 512];
__device__ float g_scores[Bn * Sn];
__device__ float g_weights[Bn * Sn];
__device__ float g_partial[Bn * NCHUNK * 1024];
__device__ int   g_maskmode;
// W_enc staged as bf16 hi/lo, SW128-swizzled [n][k] tiles.
// 32 pieces (nc 0..1 x kc 0..15), each 64KB = [hi 32KB][lo 32KB]
__device__ __align__(16) unsigned char g_Bt[32 * 65536];

// ------------------------------ helpers -------------------------------------
__device__ __forceinline__ uint32_t smem_u32(const void* p) {
    uint32_t a;
    asm("{ .reg .u64 t; cvta.to.shared.u64 t, %1; cvt.u32.u64 %0, t; }"
        : "=r"(a) : "l"(p));
    return a;
}
__device__ __forceinline__ uint32_t swz(uint32_t off) {
    return off ^ ((off >> 3) & 0x70);
}
__device__ __forceinline__ void ldsm4(uint32_t* r, uint32_t addr) {
    asm volatile("ldmatrix.sync.aligned.m8n8.x4.shared.b16 {%0,%1,%2,%3}, [%4];"
                 : "=r"(r[0]), "=r"(r[1]), "=r"(r[2]), "=r"(r[3]) : "r"(addr));
}
__device__ __forceinline__ void mma_bf16(float* c, const uint32_t* a,
                                         uint32_t b0, uint32_t b1) {
    asm("mma.sync.aligned.m16n8k16.row.col.f32.bf16.bf16.f32 "
        "{%0,%1,%2,%3},{%4,%5,%6,%7},{%8,%9},{%0,%1,%2,%3};"
        : "+f"(c[0]), "+f"(c[1]), "+f"(c[2]), "+f"(c[3])
        : "r"(a[0]), "r"(a[1]), "r"(a[2]), "r"(a[3]), "r"(b0), "r"(b1));
}
__device__ __forceinline__ void cp16(uint32_t dst, const void* src) {
    asm volatile("cp.async.cg.shared.global [%0], [%1], 16;"
                 :: "r"(dst), "l"(src));
}
__device__ __forceinline__ void cp_commit() {
    asm volatile("cp.async.commit_group;" ::: "memory");
}
__device__ __forceinline__ void cp_wait0() {
    asm volatile("cp.async.wait_group 0;" ::: "memory");
}

// ------------------------------ mask detect ---------------------------------
__global__ void k_detect_mask(const unsigned char* __restrict__ m) {
    int t = threadIdx.x;
    int found = 0;
    for (int i = 4 * t + 1; i < Bn * Sn; i += 1024)
        if (m[i]) found = 1;
    found = __syncthreads_or(found);
    if (t == 0) g_maskmode = found;
}

// ------------------------------ k0: decoder att -----------------------------
__global__ void k0_decoder(const float* __restrict__ dec,
                           const float* __restrict__ Wd,
                           const float* __restrict__ bd,
                           const float* __restrict__ be) {
    int b = blockIdx.x, t = threadIdx.x;
    __shared__ float ds[512];
    ds[t]       = dec[b * 512 + t];
    ds[t + 256] = dec[b * 512 + t + 256];
    __syncthreads();
#pragma unroll
    for (int a0 = 0; a0 < 2; a0++) {
        int a = t + a0 * 256;
        float acc = be[a] + bd[a];
#pragma unroll 8
        for (int h = 0; h < 512; h++) acc += ds[h] * Wd[h * 512 + a];
        g_D[b * 512 + a] = acc;
    }
}

// ------------------------------ kW: stage W_enc -----------------------------
__global__ void kW_convert(const float* __restrict__ We) {
    int gid = blockIdx.x * 256 + threadIdx.x;   // 0..524287
    int k = gid >> 9, n = gid & 511;
    float w = We[gid];
    __nv_bfloat16 hi = __float2bfloat16(w);
    float rem = w - __bfloat162float(hi);
    __nv_bfloat16 lo = __float2bfloat16(rem);
    int kc = k >> 6, kl = k & 63, nc = n >> 8, nl = n & 255;
    int piece = nc * 16 + kc;
    uint32_t sw = swz((uint32_t)nl * 128u + (uint32_t)kl * 2u);
    unsigned char* basep = g_Bt + (size_t)piece * 65536;
    *(__nv_bfloat16*)(basep + sw)         = hi;
    *(__nv_bfloat16*)(basep + 32768 + sw) = lo;
}

// ------------------------------ K1: HMMA scores -----------------------------
// Dynamic smem: 2 buffers x (A 32KB + B 64KB) = 192KB
#define SA_OFF 0
#define SB_OFF 32768
#define BUFSTRIDE 98304
#define SM_SMEM (2 * BUFSTRIDE)
#define K1_THREADS 512

__device__ __forceinline__ void convertA64(const float* __restrict__ enc,
                                           int r0, int kc, char* abuf, int tid) {
    const float4* src = (const float4*)(enc + (size_t)r0 * 1024 + kc * 64);
#pragma unroll
    for (int i = 0; i < 4; i++) {
        int idx = i * K1_THREADS + tid;    // 0..2047
        int row = idx >> 4, kq = idx & 15;
        float4 f = src[(size_t)row * 256 + kq];
        __nv_bfloat16 h0 = __float2bfloat16(f.x), h1 = __float2bfloat16(f.y);
        __nv_bfloat16 h2 = __float2bfloat16(f.z), h3 = __float2bfloat16(f.w);
        __nv_bfloat16 l0 = __float2bfloat16(f.x - __bfloat162float(h0));
        __nv_bfloat16 l1 = __float2bfloat16(f.y - __bfloat162float(h1));
        __nv_bfloat16 l2 = __float2bfloat16(f.z - __bfloat162float(h2));
        __nv_bfloat16 l3 = __float2bfloat16(f.w - __bfloat162float(h3));
        __nv_bfloat162 ph0 = __nv_bfloat162(h0, h1), ph1 = __nv_bfloat162(h2, h3);
        __nv_bfloat162 pl0 = __nv_bfloat162(l0, l1), pl1 = __nv_bfloat162(l2, l3);
        uint32_t sw = swz((uint32_t)row * 128u + (uint32_t)kq * 8u);
        *(uint2*)(abuf + sw)         = make_uint2(*(uint32_t*)&ph0, *(uint32_t*)&ph1);
        *(uint2*)(abuf + 16384 + sw) = make_uint2(*(uint32_t*)&pl0, *(uint32_t*)&pl1);
    }
}

__global__ __launch_bounds__(K1_THREADS)
void k1_mma(const float* __restrict__ enc,
            const float* __restrict__ Wa,
            const float* __restrict__ ba) {
    extern __shared__ char smem[];
    __shared__ float s_sc[128];
    const uint32_t sb = smem_u32(smem);
    const int tid = threadIdx.x;
    const int wid = tid >> 5, lid = tid & 31;
    const int r0 = blockIdx.x * 128;
    const int b  = r0 >> 11;
    const int wm = wid & 3;            // m group: rows wm*32..+32
    const int wn = wid >> 2;           // n group: cols wn*64..+64
    const int r4 = lid >> 2, q = lid & 3;

    // per-lane invariant fragment offsets (within plane, before swizzle)
    const uint32_t aoffb = (uint32_t)(wm * 32 + (lid & 15)) * 128u + ((lid >> 4) * 16u);
    const uint32_t boffb = (uint32_t)(wn * 64 + (lid & 7) + ((lid >> 4) << 3)) * 128u +
                           (((lid >> 3) & 1) * 16u);

    if (tid < 128) s_sc[tid] = 0.f;

    for (int nc = 0; nc < 2; nc++) {
        float acc[2][8][4];
#pragma unroll
        for (int mt = 0; mt < 2; mt++)
#pragma unroll
            for (int nt = 0; nt < 8; nt++)
#pragma unroll
                for (int v = 0; v < 4; v++) acc[mt][nt][v] = 0.f;

        // prologue: stage kc=0
        {
            const unsigned char* src = g_Bt + (size_t)(nc * 16) * 65536;
#pragma unroll
            for (int v = 0; v < 8; v++)
                cp16(sb + SB_OFF + (v * K1_THREADS + tid) * 16,
                     src + (size_t)(v * K1_THREADS + tid) * 16);
            cp_commit();
            convertA64(enc, r0, 0, smem + SA_OFF, tid);
            cp_wait0();
        }
        __syncthreads();

        for (int kc = 0; kc < 16; kc++) {
            const int cur = kc & 1;
            const uint32_t aB = sb + cur * BUFSTRIDE + SA_OFF;
            const uint32_t bB = sb + cur * BUFSTRIDE + SB_OFF;

            if (kc < 15) {  // async-stage next B while MMA runs
                const unsigned char* src = g_Bt + (size_t)(nc * 16 + kc + 1) * 65536;
                uint32_t dst = sb + (cur ^ 1) * BUFSTRIDE + SB_OFF;
#pragma unroll
                for (int v = 0; v < 8; v++)
                    cp16(dst + (v * K1_THREADS + tid) * 16,
                         src + (size_t)(v * K1_THREADS + tid) * 16);
                cp_commit();
            }

#pragma unroll
            for (int kk = 0; kk < 4; kk++) {
                uint32_t ah[2][4], al[2][4];
#pragma unroll
                for (int mt = 0; mt < 2; mt++) {
                    uint32_t off = aoffb + (uint32_t)(mt * 16) * 128u + kk * 32u;
                    ldsm4(ah[mt], aB + swz(off));
                    ldsm4(al[mt], aB + 16384 + swz(off));
                }
#pragma unroll
                for (int ntp = 0; ntp < 4; ntp++) {
                    uint32_t off = boffb + (uint32_t)(ntp * 16) * 128u + kk * 32u;
                    uint32_t bh[4], bl[4];
                    ldsm4(bh, bB + swz(off));
                    ldsm4(bl, bB + 32768 + swz(off));
#pragma unroll
                    for (int mt = 0; mt < 2; mt++) {
                        mma_bf16(acc[mt][2 * ntp],     ah[mt], bh[0], bh[1]);
                        mma_bf16(acc[mt][2 * ntp],     al[mt], bh[0], bh[1]);
                        mma_bf16(acc[mt][2 * ntp],     ah[mt], bl[0], bl[1]);
                        mma_bf16(acc[mt][2 * ntp + 1], ah[mt], bh[2], bh[3]);
                        mma_bf16(acc[mt][2 * ntp + 1], al[mt], bh[2], bh[3]);
                        mma_bf16(acc[mt][2 * ntp + 1], ah[mt], bl[2], bl[3]);
                    }
                }
            }

            if (kc < 15)
                convertA64(enc, r0, kc + 1, smem + (cur ^ 1) * BUFSTRIDE + SA_OFF, tid);
            cp_wait0();
            __syncthreads();
        }

        // epilogue: score += tanh(acc + D[col]) * Wa[col]
#pragma unroll
        for (int mt = 0; mt < 2; mt++) {
            float p0 = 0.f, p1 = 0.f;
#pragma unroll
            for (int nt = 0; nt < 8; nt++) {
                int c0 = nc * 256 + wn * 64 + nt * 8 + q * 2;
                float d0v = g_D[b * 512 + c0], d1v = g_D[b * 512 + c0 + 1];
                float w0 = Wa[c0], w1 = Wa[c0 + 1];
                p0 += tanhf(acc[mt][nt][0] + d0v) * w0 + tanhf(acc[mt][nt][1] + d1v) * w1;
                p1 += tanhf(acc[mt][nt][2] + d0v) * w0 + tanhf(acc[mt][nt][3] + d1v) * w1;
            }
            p0 += __shfl_xor_sync(0xffffffffu, p0, 1);
            p0 += __shfl_xor_sync(0xffffffffu, p0, 2);
            p1 += __shfl_xor_sync(0xffffffffu, p1, 1);
            p1 += __shfl_xor_sync(0xffffffffu, p1, 2);
            if (q == 0) {
                atomicAdd(&s_sc[wm * 32 + mt * 16 + r4], p0);
                atomicAdd(&s_sc[wm * 32 + mt * 16 + r4 + 8], p1);
            }
        }
        __syncthreads();
    }

    if (tid < 128) g_scores[r0 + tid] = s_sc[tid] + ba[0];
}

// ------------------------------ k2a: softmax --------------------------------
__global__ void k2a_softmax(const void* __restrict__ masks) {
    int b = blockIdx.x, t = threadIdx.x;
    __shared__ float sm[2048];
    __shared__ float red[256];
    const float NEG_INF = __int_as_float(0xff800000);
    const int mode = g_maskmode;
    const unsigned int*  m32 = (const unsigned int*)masks;
    const unsigned char* m8  = (const unsigned char*)masks;

    float lmax = NEG_INF;
#pragma unroll
    for (int v = 0; v < 8; v++) {
        int idx = v * 256 + t;
        float sc = g_scores[b * 2048 + idx];
        bool masked = mode ? (m8[b * 2048 + idx] != 0) : (m32[b * 2048 + idx] != 0u);
        if (masked) sc = NEG_INF;
        sm[idx] = sc;
        lmax = fmaxf(lmax, sc);
    }
    red[t] = lmax;
    __syncthreads();
    for (int o = 128; o > 0; o >>= 1) {
        if (t < o) red[t] = fmaxf(red[t], red[t + o]);
        __syncthreads();
    }
    float bmax = red[0];
    __syncthreads();

    float lsum = 0.f;
#pragma unroll
    for (int v = 0; v < 8; v++) {
        int idx = v * 256 + t;
        float e = expf(sm[idx] - bmax);
        sm[idx] = e;
        lsum += e;
    }
    red[t] = lsum;
    __syncthreads();
    for (int o = 128; o > 0; o >>= 1) {
        if (t < o) red[t] += red[t + o];
        __syncthreads();
    }
    float inv = 1.f / red[0];
#pragma unroll
    for (int v = 0; v < 8; v++) {
        int idx = v * 256 + t;
        g_weights[b * 2048 + idx] = sm[idx] * inv;
    }
}

// ------------------------------ k2b: weighted sum ---------------------------
__global__ void k2b_partial(const float* __restrict__ enc) {
    int ch = blockIdx.x, b = blockIdx.y, t = threadIdx.x;
    __shared__ float w[128];
    if (t < 128) w[t] = g_weights[b * 2048 + ch * 128 + t];
    __syncthreads();

    const float4* rowbase =
        reinterpret_cast<const float4*>(enc) + (size_t)(b * 2048 + ch * 128) * 256;
    float4 acc = make_float4(0.f, 0.f, 0.f, 0.f);
    for (int si = 0; si < 128; si++) {
        float wv = w[si];
        if (wv != 0.f) {
            float4 v = rowbase[(size_t)si * 256 + t];
            acc.x += wv * v.x; acc.y += wv * v.y;
            acc.z += wv * v.z; acc.w += wv * v.w;
        }
    }
    reinterpret_cast<float4*>(g_partial)[(b * NCHUNK + ch) * 256 + t] = acc;
}

// ------------------------------ k2c: final GEMV -----------------------------
__global__ void k2c_context(const float* __restrict__ We,
                            const float* __restrict__ be,
                            float* __restrict__ out) {
    int b = blockIdx.x, t = threadIdx.x;
    __shared__ float ctx[1024];
    float4 s = make_float4(0.f, 0.f, 0.f, 0.f);
#pragma unroll
    for (int chn = 0; chn < NCHUNK; chn++) {
        float4 v = reinterpret_cast<const float4*>(g_partial)[(b * NCHUNK + chn) * 256 + t];
        s.x += v.x; s.y += v.y; s.z += v.z; s.w += v.w;
    }
    reinterpret_cast<float4*>(ctx)[t] = s;
    __syncthreads();

    float acc0 = be[t], acc1 = be[t + 256];
#pragma unroll 4
    for (int k = 0; k < 1024; k++) {
        float c = ctx[k];
        const float* wr = We + k * 512;
        acc0 += c * wr[t];
        acc1 += c * wr[t + 256];
    }
    out[b * 512 + t]       = acc0;
    out[b * 512 + t + 256] = acc1;
}

// ---------------------------------------------------------------------------
extern "C" void kernel_launch(void* const* d_in, const int* in_sizes, int n_in,
                              void* d_out, int out_size) {
    const float*         enc   = (const float*)d_in[0];
    const float*         dec   = (const float*)d_in[1];
    const unsigned char* masks = (const unsigned char*)d_in[2];
    const float*         We    = (const float*)d_in[3];
    const float*         be    = (const float*)d_in[4];
    const float*         Wd    = (const float*)d_in[5];
    const float*         bd    = (const float*)d_in[6];
    const float*         Wa    = (const float*)d_in[7];
    const float*         ba    = (const float*)d_in[8];
    float* out = (float*)d_out;

    static int configured = 0;
    if (!configured) {
        cudaFuncSetAttribute(k1_mma, cudaFuncAttributeMaxDynamicSharedMemorySize, SM_SMEM);
        configured = 1;
    }

    k_detect_mask<<<1, 256>>>(masks);
    k0_decoder<<<Bn, 256>>>(dec, Wd, bd, be);
    kW_convert<<<2048, 256>>>(We);
    k1_mma<<<512, K1_THREADS, SM_SMEM>>>(enc, Wa, ba);
    k2a_softmax<<<Bn, 256>>>((const void*)masks);
    dim3 g2b(NCHUNK, Bn);
    k2b_partial<<<g2b, 256>>>(enc);
    k2c_context<<<Bn, 256>>>(We, be, out);
}

// round 7
// speedup vs baseline: 1.9614x; 1.0307x over previous
#include <cuda_runtime.h>
#include <cuda_bf16.h>
#include <math.h>
#include <stdint.h>

#define Bn 32
#define Sn 2048
#define NCHUNK 16

// ------------------------------ device scratch ------------------------------
__device__ float g_D[Bn * 512];
__device__ float g_scores[Bn * Sn];
__device__ float g_weights[Bn * Sn];
__device__ float g_partial[Bn * NCHUNK * 1024];
__device__ int   g_maskmode;
// W_enc staged as bf16 hi/lo, SW128-swizzled [n][k] tiles.
// 32 pieces (nc 0..1 x kc 0..15), each 64KB = [hi 32KB][lo 32KB]
__device__ __align__(16) unsigned char g_Bt[32 * 65536];

// ------------------------------ helpers -------------------------------------
__device__ __forceinline__ uint32_t smem_u32(const void* p) {
    uint32_t a;
    asm("{ .reg .u64 t; cvta.to.shared.u64 t, %1; cvt.u32.u64 %0, t; }"
        : "=r"(a) : "l"(p));
    return a;
}
__device__ __forceinline__ uint32_t swz(uint32_t off) {
    return off ^ ((off >> 3) & 0x70);
}
__device__ __forceinline__ void ldsm4(uint32_t* r, uint32_t addr) {
    asm volatile("ldmatrix.sync.aligned.m8n8.x4.shared.b16 {%0,%1,%2,%3}, [%4];"
                 : "=r"(r[0]), "=r"(r[1]), "=r"(r[2]), "=r"(r[3]) : "r"(addr));
}
__device__ __forceinline__ void mma_bf16(float* c, const uint32_t* a,
                                         uint32_t b0, uint32_t b1) {
    asm("mma.sync.aligned.m16n8k16.row.col.f32.bf16.bf16.f32 "
        "{%0,%1,%2,%3},{%4,%5,%6,%7},{%8,%9},{%0,%1,%2,%3};"
        : "+f"(c[0]), "+f"(c[1]), "+f"(c[2]), "+f"(c[3])
        : "r"(a[0]), "r"(a[1]), "r"(a[2]), "r"(a[3]), "r"(b0), "r"(b1));
}
__device__ __forceinline__ void cp16(uint32_t dst, const void* src) {
    asm volatile("cp.async.cg.shared.global [%0], [%1], 16;"
                 :: "r"(dst), "l"(src));
}
__device__ __forceinline__ void cp_commit() {
    asm volatile("cp.async.commit_group;" ::: "memory");
}
__device__ __forceinline__ void cp_wait0() {
    asm volatile("cp.async.wait_group 0;" ::: "memory");
}

// ------------------------------ mask detect ---------------------------------
__global__ void k_detect_mask(const unsigned char* __restrict__ m) {
    int t = threadIdx.x;
    int found = 0;
    for (int i = 4 * t + 1; i < Bn * Sn; i += 1024)
        if (m[i]) found = 1;
    found = __syncthreads_or(found);
    if (t == 0) g_maskmode = found;
}

// ------------------------------ k0: decoder att -----------------------------
__global__ void k0_decoder(const float* __restrict__ dec,
                           const float* __restrict__ Wd,
                           const float* __restrict__ bd,
                           const float* __restrict__ be) {
    int b = blockIdx.x, t = threadIdx.x;
    __shared__ float ds[512];
    ds[t]       = dec[b * 512 + t];
    ds[t + 256] = dec[b * 512 + t + 256];
    __syncthreads();
#pragma unroll
    for (int a0 = 0; a0 < 2; a0++) {
        int a = t + a0 * 256;
        float acc = be[a] + bd[a];
#pragma unroll 8
        for (int h = 0; h < 512; h++) acc += ds[h] * Wd[h * 512 + a];
        g_D[b * 512 + a] = acc;
    }
}

// ------------------------------ kW: stage W_enc -----------------------------
__global__ void kW_convert(const float* __restrict__ We) {
    int gid = blockIdx.x * 256 + threadIdx.x;   // 0..524287
    int k = gid >> 9, n = gid & 511;
    float w = We[gid];
    __nv_bfloat16 hi = __float2bfloat16(w);
    float rem = w - __bfloat162float(hi);
    __nv_bfloat16 lo = __float2bfloat16(rem);
    int kc = k >> 6, kl = k & 63, nc = n >> 8, nl = n & 255;
    int piece = nc * 16 + kc;
    uint32_t sw = swz((uint32_t)nl * 128u + (uint32_t)kl * 2u);
    unsigned char* basep = g_Bt + (size_t)piece * 65536;
    *(__nv_bfloat16*)(basep + sw)         = hi;
    *(__nv_bfloat16*)(basep + 32768 + sw) = lo;
}

// ------------------------------ K1: HMMA scores -----------------------------
// Dynamic smem: 2 buffers x (A 32KB + B 64KB) = 192KB
#define SA_OFF 0
#define SB_OFF 32768
#define BUFSTRIDE 98304
#define SM_SMEM (2 * BUFSTRIDE)
#define K1_THREADS 512

// phase 1: issue global loads for A chunk kc into registers
__device__ __forceinline__ void loadA64(const float* __restrict__ enc,
                                        int r0, int kc, float4* f, int tid) {
    const float4* src = (const float4*)(enc + (size_t)r0 * 1024 + kc * 64);
#pragma unroll
    for (int i = 0; i < 4; i++) {
        int idx = i * K1_THREADS + tid;    // 0..2047
        int row = idx >> 4, kq = idx & 15;
        f[i] = src[(size_t)row * 256 + kq];
    }
}
// phase 2: convert + store to swizzled smem
__device__ __forceinline__ void storeA64(const float4* f, char* abuf, int tid) {
#pragma unroll
    for (int i = 0; i < 4; i++) {
        int idx = i * K1_THREADS + tid;
        int row = idx >> 4, kq = idx & 15;
        float4 v = f[i];
        __nv_bfloat16 h0 = __float2bfloat16(v.x), h1 = __float2bfloat16(v.y);
        __nv_bfloat16 h2 = __float2bfloat16(v.z), h3 = __float2bfloat16(v.w);
        __nv_bfloat16 l0 = __float2bfloat16(v.x - __bfloat162float(h0));
        __nv_bfloat16 l1 = __float2bfloat16(v.y - __bfloat162float(h1));
        __nv_bfloat16 l2 = __float2bfloat16(v.z - __bfloat162float(h2));
        __nv_bfloat16 l3 = __float2bfloat16(v.w - __bfloat162float(h3));
        __nv_bfloat162 ph0 = __nv_bfloat162(h0, h1), ph1 = __nv_bfloat162(h2, h3);
        __nv_bfloat162 pl0 = __nv_bfloat162(l0, l1), pl1 = __nv_bfloat162(l2, l3);
        uint32_t sw = swz((uint32_t)row * 128u + (uint32_t)kq * 8u);
        *(uint2*)(abuf + sw)         = make_uint2(*(uint32_t*)&ph0, *(uint32_t*)&ph1);
        *(uint2*)(abuf + 16384 + sw) = make_uint2(*(uint32_t*)&pl0, *(uint32_t*)&pl1);
    }
}

__global__ __launch_bounds__(K1_THREADS)
void k1_mma(const float* __restrict__ enc,
            const float* __restrict__ Wa,
            const float* __restrict__ ba) {
    extern __shared__ char smem[];
    __shared__ float s_sc[128];
    const uint32_t sb = smem_u32(smem);
    const int tid = threadIdx.x;
    const int wid = tid >> 5, lid = tid & 31;
    const int r0 = blockIdx.x * 128;
    const int b  = r0 >> 11;
    const int wm = wid & 3;            // m group: rows wm*32..+32
    const int wn = wid >> 2;           // n group: cols wn*64..+64
    const int r4 = lid >> 2, q = lid & 3;

    const uint32_t aoffb = (uint32_t)(wm * 32 + (lid & 15)) * 128u + ((lid >> 4) * 16u);
    const uint32_t boffb = (uint32_t)(wn * 64 + (lid & 7) + ((lid >> 4) << 3)) * 128u +
                           (((lid >> 3) & 1) * 16u);

    if (tid < 128) s_sc[tid] = 0.f;

    for (int nc = 0; nc < 2; nc++) {
        float acc[2][8][4];
#pragma unroll
        for (int mt = 0; mt < 2; mt++)
#pragma unroll
            for (int nt = 0; nt < 8; nt++)
#pragma unroll
                for (int v = 0; v < 4; v++) acc[mt][nt][v] = 0.f;

        float4 aregs[4];

        // prologue: stage kc=0 (A via regs, B via cp.async)
        {
            loadA64(enc, r0, 0, aregs, tid);
            const unsigned char* src = g_Bt + (size_t)(nc * 16) * 65536;
#pragma unroll
            for (int v = 0; v < 8; v++)
                cp16(sb + SB_OFF + (v * K1_THREADS + tid) * 16,
                     src + (size_t)(v * K1_THREADS + tid) * 16);
            cp_commit();
            storeA64(aregs, smem + SA_OFF, tid);
            cp_wait0();
        }
        __syncthreads();

        for (int kc = 0; kc < 16; kc++) {
            const int cur = kc & 1;
            const uint32_t aB = sb + cur * BUFSTRIDE + SA_OFF;
            const uint32_t bB = sb + cur * BUFSTRIDE + SB_OFF;

            if (kc < 15) {
                // issue next-chunk A loads early (latency hidden under MMAs)
                loadA64(enc, r0, kc + 1, aregs, tid);
                // async-stage next B while MMA runs
                const unsigned char* src = g_Bt + (size_t)(nc * 16 + kc + 1) * 65536;
                uint32_t dst = sb + (cur ^ 1) * BUFSTRIDE + SB_OFF;
#pragma unroll
                for (int v = 0; v < 8; v++)
                    cp16(dst + (v * K1_THREADS + tid) * 16,
                         src + (size_t)(v * K1_THREADS + tid) * 16);
                cp_commit();
            }

#pragma unroll
            for (int kk = 0; kk < 4; kk++) {
                uint32_t ah[2][4], al[2][4];
#pragma unroll
                for (int mt = 0; mt < 2; mt++) {
                    uint32_t off = aoffb + (uint32_t)(mt * 16) * 128u + kk * 32u;
                    ldsm4(ah[mt], aB + swz(off));
                    ldsm4(al[mt], aB + 16384 + swz(off));
                }
#pragma unroll
                for (int ntp = 0; ntp < 4; ntp++) {
                    uint32_t off = boffb + (uint32_t)(ntp * 16) * 128u + kk * 32u;
                    uint32_t bh[4], bl[4];
                    ldsm4(bh, bB + swz(off));
                    ldsm4(bl, bB + 32768 + swz(off));
#pragma unroll
                    for (int mt = 0; mt < 2; mt++) {
                        mma_bf16(acc[mt][2 * ntp],     ah[mt], bh[0], bh[1]);
                        mma_bf16(acc[mt][2 * ntp],     al[mt], bh[0], bh[1]);
                        mma_bf16(acc[mt][2 * ntp],     ah[mt], bl[0], bl[1]);
                        mma_bf16(acc[mt][2 * ntp + 1], ah[mt], bh[2], bh[3]);
                        mma_bf16(acc[mt][2 * ntp + 1], al[mt], bh[2], bh[3]);
                        mma_bf16(acc[mt][2 * ntp + 1], ah[mt], bl[2], bl[3]);
                    }
                }
            }

            if (kc < 15)
                storeA64(aregs, smem + (cur ^ 1) * BUFSTRIDE + SA_OFF, tid);
            cp_wait0();
            __syncthreads();
        }

        // epilogue: score += tanh(acc + D[col]) * Wa[col]
#pragma unroll
        for (int mt = 0; mt < 2; mt++) {
            float p0 = 0.f, p1 = 0.f;
#pragma unroll
            for (int nt = 0; nt < 8; nt++) {
                int c0 = nc * 256 + wn * 64 + nt * 8 + q * 2;
                float d0v = g_D[b * 512 + c0], d1v = g_D[b * 512 + c0 + 1];
                float w0 = Wa[c0], w1 = Wa[c0 + 1];
                p0 += tanhf(acc[mt][nt][0] + d0v) * w0 + tanhf(acc[mt][nt][1] + d1v) * w1;
                p1 += tanhf(acc[mt][nt][2] + d0v) * w0 + tanhf(acc[mt][nt][3] + d1v) * w1;
            }
            p0 += __shfl_xor_sync(0xffffffffu, p0, 1);
            p0 += __shfl_xor_sync(0xffffffffu, p0, 2);
            p1 += __shfl_xor_sync(0xffffffffu, p1, 1);
            p1 += __shfl_xor_sync(0xffffffffu, p1, 2);
            if (q == 0) {
                atomicAdd(&s_sc[wm * 32 + mt * 16 + r4], p0);
                atomicAdd(&s_sc[wm * 32 + mt * 16 + r4 + 8], p1);
            }
        }
        __syncthreads();
    }

    if (tid < 128) g_scores[r0 + tid] = s_sc[tid] + ba[0];
}

// ------------------------------ k2a: softmax --------------------------------
__global__ void k2a_softmax(const void* __restrict__ masks) {
    int b = blockIdx.x, t = threadIdx.x;
    __shared__ float sm[2048];
    __shared__ float red[256];
    const float NEG_INF = __int_as_float(0xff800000);
    const int mode = g_maskmode;
    const unsigned int*  m32 = (const unsigned int*)masks;
    const unsigned char* m8  = (const unsigned char*)masks;

    float lmax = NEG_INF;
#pragma unroll
    for (int v = 0; v < 8; v++) {
        int idx = v * 256 + t;
        float sc = g_scores[b * 2048 + idx];
        bool masked = mode ? (m8[b * 2048 + idx] != 0) : (m32[b * 2048 + idx] != 0u);
        if (masked) sc = NEG_INF;
        sm[idx] = sc;
        lmax = fmaxf(lmax, sc);
    }
    red[t] = lmax;
    __syncthreads();
    for (int o = 128; o > 0; o >>= 1) {
        if (t < o) red[t] = fmaxf(red[t], red[t + o]);
        __syncthreads();
    }
    float bmax = red[0];
    __syncthreads();

    float lsum = 0.f;
#pragma unroll
    for (int v = 0; v < 8; v++) {
        int idx = v * 256 + t;
        float e = expf(sm[idx] - bmax);
        sm[idx] = e;
        lsum += e;
    }
    red[t] = lsum;
    __syncthreads();
    for (int o = 128; o > 0; o >>= 1) {
        if (t < o) red[t] += red[t + o];
        __syncthreads();
    }
    float inv = 1.f / red[0];
#pragma unroll
    for (int v = 0; v < 8; v++) {
        int idx = v * 256 + t;
        g_weights[b * 2048 + idx] = sm[idx] * inv;
    }
}

// ------------------------------ k2b: weighted sum ---------------------------
__global__ void k2b_partial(const float* __restrict__ enc) {
    int ch = blockIdx.x, b = blockIdx.y, t = threadIdx.x;
    __shared__ float w[128];
    if (t < 128) w[t] = g_weights[b * 2048 + ch * 128 + t];
    __syncthreads();

    const float4* rowbase =
        reinterpret_cast<const float4*>(enc) + (size_t)(b * 2048 + ch * 128) * 256;
    float4 acc = make_float4(0.f, 0.f, 0.f, 0.f);
    for (int si = 0; si < 128; si++) {
        float wv = w[si];
        if (wv != 0.f) {
            float4 v = rowbase[(size_t)si * 256 + t];
            acc.x += wv * v.x; acc.y += wv * v.y;
            acc.z += wv * v.z; acc.w += wv * v.w;
        }
    }
    reinterpret_cast<float4*>(g_partial)[(b * NCHUNK + ch) * 256 + t] = acc;
}

// ------------------------------ k2c: final GEMV -----------------------------
__global__ void k2c_context(const float* __restrict__ We,
                            const float* __restrict__ be,
                            float* __restrict__ out) {
    int b = blockIdx.x, t = threadIdx.x;
    __shared__ float ctx[1024];
    float4 s = make_float4(0.f, 0.f, 0.f, 0.f);
#pragma unroll
    for (int chn = 0; chn < NCHUNK; chn++) {
        float4 v = reinterpret_cast<const float4*>(g_partial)[(b * NCHUNK + chn) * 256 + t];
        s.x += v.x; s.y += v.y; s.z += v.z; s.w += v.w;
    }
    reinterpret_cast<float4*>(ctx)[t] = s;
    __syncthreads();

    float acc0 = be[t], acc1 = be[t + 256];
#pragma unroll 4
    for (int k = 0; k < 1024; k++) {
        float c = ctx[k];
        const float* wr = We + k * 512;
        acc0 += c * wr[t];
        acc1 += c * wr[t + 256];
    }
    out[b * 512 + t]       = acc0;
    out[b * 512 + t + 256] = acc1;
}

// ---------------------------------------------------------------------------
extern "C" void kernel_launch(void* const* d_in, const int* in_sizes, int n_in,
                              void* d_out, int out_size) {
    const float*         enc   = (const float*)d_in[0];
    const float*         dec   = (const float*)d_in[1];
    const unsigned char* masks = (const unsigned char*)d_in[2];
    const float*         We    = (const float*)d_in[3];
    const float*         be    = (const float*)d_in[4];
    const float*         Wd    = (const float*)d_in[5];
    const float*         bd    = (const float*)d_in[6];
    const float*         Wa    = (const float*)d_in[7];
    const float*         ba    = (const float*)d_in[8];
    float* out = (float*)d_out;

    static int configured = 0;
    if (!configured) {
        cudaFuncSetAttribute(k1_mma, cudaFuncAttributeMaxDynamicSharedMemorySize, SM_SMEM);
        configured = 1;
    }

    k_detect_mask<<<1, 256>>>(masks);
    k0_decoder<<<Bn, 256>>>(dec, Wd, bd, be);
    kW_convert<<<2048, 256>>>(We);
    k1_mma<<<512, K1_THREADS, SM_SMEM>>>(enc, Wa, ba);
    k2a_softmax<<<Bn, 256>>>((const void*)masks);
    dim3 g2b(NCHUNK, Bn);
    k2b_partial<<<g2b, 256>>>(enc);
    k2c_context<<<Bn, 256>>>(We, be, out);
}